// round 2
// baseline (speedup 1.0000x reference)
#include <cuda_runtime.h>
#include <cuda_bf16.h>

// CenterLoss: loss = LAMBDA_C * mean_b sum_d (features[b,d] - centers[labels[b],d])^2
// B=65536, D=256, C=100000. HBM-bound gather + reduction.

#define BATCH    65536
#define FEAT_DIM 256
#define GRID1    1184          // 8 CTAs/SM * 148 SMs
#define BLOCK1   256           // 8 warps per CTA, 1 warp handles 1 row per iter

__device__ float g_partials[GRID1];

__global__ __launch_bounds__(BLOCK1) void center_loss_stage1(
    const float* __restrict__ features,
    const int*   __restrict__ labels,
    const float* __restrict__ centers)
{
    const int lane   = threadIdx.x & 31;
    const int warp_g = (blockIdx.x * BLOCK1 + threadIdx.x) >> 5;
    const int nwarps = (GRID1 * BLOCK1) >> 5;

    float acc = 0.0f;

    for (int row = warp_g; row < BATCH; row += nwarps) {
        const int lbl = labels[row];
        const float4* __restrict__ f =
            reinterpret_cast<const float4*>(features + (size_t)row * FEAT_DIM);
        const float4* __restrict__ c =
            reinterpret_cast<const float4*>(centers + (size_t)lbl * FEAT_DIM);

        // 256 floats per row = 64 float4; 32 lanes * 2 float4 each.
        float4 f0 = f[lane];
        float4 f1 = f[lane + 32];
        float4 c0 = c[lane];
        float4 c1 = c[lane + 32];

        float d;
        d = f0.x - c0.x; acc = fmaf(d, d, acc);
        d = f0.y - c0.y; acc = fmaf(d, d, acc);
        d = f0.z - c0.z; acc = fmaf(d, d, acc);
        d = f0.w - c0.w; acc = fmaf(d, d, acc);
        d = f1.x - c1.x; acc = fmaf(d, d, acc);
        d = f1.y - c1.y; acc = fmaf(d, d, acc);
        d = f1.z - c1.z; acc = fmaf(d, d, acc);
        d = f1.w - c1.w; acc = fmaf(d, d, acc);
    }

    // warp reduce
    #pragma unroll
    for (int o = 16; o > 0; o >>= 1)
        acc += __shfl_xor_sync(0xFFFFFFFFu, acc, o);

    __shared__ float smem[BLOCK1 / 32];
    if (lane == 0) smem[threadIdx.x >> 5] = acc;
    __syncthreads();

    if (threadIdx.x < (BLOCK1 / 32)) {
        float v = smem[threadIdx.x];
        #pragma unroll
        for (int o = (BLOCK1 / 64); o > 0; o >>= 1)
            v += __shfl_xor_sync(0xFFu, v, o);
        if (threadIdx.x == 0) g_partials[blockIdx.x] = v;
    }
}

__global__ __launch_bounds__(1024) void center_loss_stage2(float* __restrict__ out)
{
    const int tid = threadIdx.x;
    float acc = 0.0f;
    for (int i = tid; i < GRID1; i += 1024)
        acc += g_partials[i];

    // warp reduce
    #pragma unroll
    for (int o = 16; o > 0; o >>= 1)
        acc += __shfl_xor_sync(0xFFFFFFFFu, acc, o);

    __shared__ float smem[32];
    if ((tid & 31) == 0) smem[tid >> 5] = acc;
    __syncthreads();

    if (tid < 32) {
        float v = smem[tid];
        #pragma unroll
        for (int o = 16; o > 0; o >>= 1)
            v += __shfl_xor_sync(0xFFFFFFFFu, v, o);
        if (tid == 0)
            out[0] = v * (1.0f / (float)BATCH);   // LAMBDA_C = 1.0
    }
}

extern "C" void kernel_launch(void* const* d_in, const int* in_sizes, int n_in,
                              void* d_out, int out_size)
{
    const float* features = (const float*)d_in[0];
    const int*   labels   = (const int*)  d_in[1];
    const float* centers  = (const float*)d_in[2];
    float*       out      = (float*)d_out;

    center_loss_stage1<<<GRID1, BLOCK1>>>(features, labels, centers);
    center_loss_stage2<<<1, 1024>>>(out);
}